// round 4
// baseline (speedup 1.0000x reference)
#include <cuda_runtime.h>
#include <math.h>

#define N_NODES 100000
#define N_FEATS 2048
#define HID 64
#define NLAB 40

// Scratch (no allocations allowed): 25.6 + 25.6 + 16 MB
__device__ __align__(16) float g_h1[N_NODES * HID];   // after feature SpMM + b1
__device__ __align__(16) float g_h2[N_NODES * HID];   // after adjacency SpMM
__device__ __align__(16) float g_z1[N_NODES * NLAB];  // after dense layer

__device__ __forceinline__ void red_add_v4(float* p, float a, float b, float c, float d) {
    asm volatile("red.global.add.v4.f32 [%0], {%1,%2,%3,%4};"
                 :: "l"(p), "f"(a), "f"(b), "f"(c), "f"(d) : "memory");
}

__device__ __forceinline__ int clamp_i(int i, int n) {
    i = i < 0 ? 0 : i;
    return i >= n ? n - 1 : i;
}

// Init: h1 rows = b1 broadcast, h2 = 0, out (z2 accumulator) = 0
__global__ void k_init(const float* __restrict__ b1, float* __restrict__ out) {
    int i = blockIdx.x * blockDim.x + threadIdx.x;
    if (i < N_NODES * HID) {
        g_h1[i] = __ldg(&b1[i & (HID - 1)]);
        g_h2[i] = 0.0f;
    }
    if (i < N_NODES * NLAB) out[i] = 0.0f;
}

// Feature SpMM: h1[row] += val * W1[col, :]   (16 threads per nnz, float4 each)
__global__ void k_feat(const int* __restrict__ fi, const float* __restrict__ fv,
                       const float* __restrict__ W1, int nnz) {
    int t = blockIdx.x * blockDim.x + threadIdx.x;
    if (t >= nnz * 16) return;
    int e = t >> 4, q = t & 15;
    int row = clamp_i(__ldg(&fi[e]), N_NODES);
    int col = clamp_i(__ldg(&fi[nnz + e]), N_FEATS);
    float v = __ldg(&fv[e]);
    float4 w = __ldg((const float4*)(W1 + (size_t)col * HID) + q);
    red_add_v4(&g_h1[(size_t)row * HID + q * 4], v * w.x, v * w.y, v * w.z, v * w.w);
}

// Adjacency SpMM (64-wide): h2[row] += w * h1[col]
__global__ void k_edge64(const int* __restrict__ ei, const float* __restrict__ ew, int ne) {
    int t = blockIdx.x * blockDim.x + threadIdx.x;
    if (t >= ne * 16) return;
    int e = t >> 4, q = t & 15;
    int row = clamp_i(__ldg(&ei[e]), N_NODES);
    int col = clamp_i(__ldg(&ei[ne + e]), N_NODES);
    float w = __ldg(&ew[e]);
    float4 s = __ldg((const float4*)(g_h1 + (size_t)col * HID) + q);
    red_add_v4(&g_h2[(size_t)row * HID + q * 4], w * s.x, w * s.y, w * s.z, w * s.w);
}

// Dense layer: z1 = relu(h2) @ W2 + b2. Block of 128 nodes, h staged in padded smem.
__global__ __launch_bounds__(128) void k_dense(const float* __restrict__ W2,
                                               const float* __restrict__ b2) {
    __shared__ float sW2[HID * NLAB];
    __shared__ float sb2[NLAB];
    __shared__ float sh[128 * 65];   // stride 65: conflict-free per-thread row reads
    int tid = threadIdx.x;
    for (int i = tid; i < HID * NLAB; i += 128) sW2[i] = W2[i];
    if (tid < NLAB) sb2[tid] = b2[tid];
    int base = blockIdx.x * 128 * HID;
    for (int i = tid; i < 128 * HID; i += 128) {
        int g = base + i;
        float v = (g < N_NODES * HID) ? g_h2[g] : 0.0f;
        sh[(i >> 6) * 65 + (i & 63)] = fmaxf(v, 0.0f);   // relu fused here
    }
    __syncthreads();
    int node = blockIdx.x * 128 + tid;
    if (node >= N_NODES) return;
    float acc[NLAB];
#pragma unroll
    for (int j = 0; j < NLAB; j++) acc[j] = sb2[j];
#pragma unroll 8
    for (int k = 0; k < HID; k++) {
        float hv = sh[tid * 65 + k];
#pragma unroll
        for (int j = 0; j < NLAB; j++) acc[j] += hv * sW2[k * NLAB + j];
    }
    float4* zp = (float4*)(g_z1 + (size_t)node * NLAB);
#pragma unroll
    for (int i = 0; i < NLAB / 4; i++)
        zp[i] = make_float4(acc[4 * i], acc[4 * i + 1], acc[4 * i + 2], acc[4 * i + 3]);
}

// Adjacency SpMM (40-wide): out[row] += w * z1[col]. Thread per (edge, float4): 10/edge.
__global__ void k_edge40(const int* __restrict__ ei, const float* __restrict__ ew,
                         float* __restrict__ out, int ne) {
    int t = blockIdx.x * blockDim.x + threadIdx.x;
    if (t >= ne * 10) return;
    int e = t / 10;
    int q = t - e * 10;
    int row = clamp_i(__ldg(&ei[e]), N_NODES);
    int col = clamp_i(__ldg(&ei[ne + e]), N_NODES);
    float w = __ldg(&ew[e]);
    float4 s = __ldg((const float4*)(g_z1 + (size_t)col * NLAB) + q);
    red_add_v4(out + (size_t)row * NLAB + q * 4, w * s.x, w * s.y, w * s.z, w * s.w);
}

// In-place log-softmax over 40 labels: one warp per node.
__global__ void k_lsm(float* __restrict__ out) {
    int gw = (blockIdx.x * blockDim.x + threadIdx.x) >> 5;
    int lane = threadIdx.x & 31;
    if (gw >= N_NODES) return;
    float* r = out + (size_t)gw * NLAB;
    float v0 = r[lane];
    float v1 = (lane < 8) ? r[32 + lane] : -1e30f;
    float m = fmaxf(v0, v1);
#pragma unroll
    for (int o = 16; o; o >>= 1) m = fmaxf(m, __shfl_xor_sync(0xFFFFFFFFu, m, o));
    float s = expf(v0 - m) + ((lane < 8) ? expf(v1 - m) : 0.0f);
#pragma unroll
    for (int o = 16; o; o >>= 1) s += __shfl_xor_sync(0xFFFFFFFFu, s, o);
    float l = m + logf(s);
    r[lane] = v0 - l;
    if (lane < 8) r[32 + lane] = v1 - l;
}

extern "C" void kernel_launch(void* const* d_in, const int* in_sizes, int n_in,
                              void* d_out, int out_size) {
    // Bind inputs by element count (all eight are pairwise distinct) so we do
    // not depend on metadata ordering. Indices are int32 (JAX x64 disabled).
    const int* fi = 0; const float* fv = 0;
    const int* ei = 0; const float* ew = 0;
    const float *W1 = 0, *b1 = 0, *W2 = 0, *b2 = 0;
    int nnz = 0, ne = 0;
    for (int i = 0; i < n_in; i++) {
        int s = in_sizes[i];
        const void* p = d_in[i];
        if (s == 2 * 2500000)            { fi = (const int*)p; }
        else if (s == 2500000)           { fv = (const float*)p; nnz = s; }
        else if (s == 2 * 1700000)       { ei = (const int*)p; }
        else if (s == 1700000)           { ew = (const float*)p; ne = s; }
        else if (s == N_FEATS * HID)     { W1 = (const float*)p; }
        else if (s == HID)               { b1 = (const float*)p; }
        else if (s == HID * NLAB)        { W2 = (const float*)p; }
        else if (s == NLAB)              { b2 = (const float*)p; }
    }
    float* out = (float*)d_out;

    k_init<<<(N_NODES * HID + 255) / 256, 256>>>(b1, out);
    k_feat<<<(nnz * 16 + 255) / 256, 256>>>(fi, fv, W1, nnz);
    k_edge64<<<(ne * 16 + 255) / 256, 256>>>(ei, ew, ne);
    k_dense<<<(N_NODES + 127) / 128, 128>>>(W2, b2);
    k_edge40<<<(ne * 10 + 255) / 256, 256>>>(ei, ew, out, ne);
    k_lsm<<<(N_NODES * 32 + 255) / 256, 256>>>(out);
}